// round 5
// baseline (speedup 1.0000x reference)
#include <cuda_runtime.h>
#include <cstdint>

#define CPB 128        // cells per tile == threads per block
#define DD  30         // features per cell: B*5 + C
#define CC  20
#define NB  2
#define LAMBDA_NOOBJ 0.5f
#define NSTAGE 2

#define TILE_FLOATS (CPB * DD)            // 3840 floats per array per tile
#define TILE_BYTES  (TILE_FLOATS * 4)     // 15360 B
// dynamic smem layout: [ sp0 | st0 | sp1 | st1 | mbar[2] ]
#define SMEM_DYN_BYTES (4 * TILE_BYTES + 2 * 8)

__device__ double       g_acc;
__device__ unsigned int g_count;

__device__ __forceinline__ uint32_t smem_u32(const void* p) {
    uint32_t a;
    asm("{ .reg .u64 t; cvta.to.shared.u64 t, %1; cvt.u32.u64 %0, t; }"
        : "=r"(a) : "l"(p));
    return a;
}

// per-cell loss; p/t point at this cell's 30 floats (smem or gmem)
__device__ __forceinline__ float cell_loss(const float* p, const float* t)
{
    float iou[NB];
    #pragma unroll
    for (int b = 0; b < NB; b++) {
        const float x1 = p[b*5+0], y1 = p[b*5+1], w1 = p[b*5+2], h1 = p[b*5+3];
        const float x2 = t[b*5+0], y2 = t[b*5+1], w2 = t[b*5+2], h2 = t[b*5+3];
        const float tlx = fmaxf(x1 - w1 * 0.5f, x2 - w2 * 0.5f);
        const float tly = fmaxf(y1 - h1 * 0.5f, y2 - h2 * 0.5f);
        const float brx = fminf(x1 + w1 * 0.5f, x2 + w2 * 0.5f);
        const float bry = fminf(y1 + h1 * 0.5f, y2 + h2 * 0.5f);
        const float iw = fmaxf(0.0f, brx - tlx);
        const float ih = fmaxf(0.0f, bry - tly);
        const float inter = iw * ih;
        const float uni = w1 * h1 + w2 * h2 - inter;
        iou[b] = inter / uni;
    }
    const int bi = (iou[1] > iou[0]) ? 1 : 0;

    float cls = 0.0f;
    float maxtc = t[10];
    int gnd = 0;
    bool has_obj = false;
    #pragma unroll
    for (int j = 0; j < CC; j++) {
        const float pc = p[10 + j];
        const float tc = t[10 + j];
        const float d = pc - tc;
        cls += d * d;
        if (tc != 0.0f) has_obj = true;
        if (tc > maxtc) { maxtc = tc; gnd = j; }
    }
    const float pg = p[10 + gnd];

    const float dx = p[bi*5+0] - t[bi*5+0];
    const float dy = p[bi*5+1] - t[bi*5+1];
    const float pos = has_obj ? (dx * dx + dy * dy) : 0.0f;

    float conf = 0.0f;
    #pragma unroll
    for (int b = 0; b < NB; b++) {
        const float cd = iou[b] * pg - iou[b];
        const float w  = (b == bi) ? 1.0f : LAMBDA_NOOBJ;
        conf += w * cd * cd;
    }
    return pos + cls + conf;
}

__global__ __launch_bounds__(CPB) void yolo_loss_kernel(
    const float* __restrict__ preds,
    const float* __restrict__ targets,
    long long n_cells,
    unsigned int n_blocks,
    float invN,
    float* __restrict__ out)
{
    extern __shared__ __align__(128) float smem[];
    float* sp[NSTAGE];
    float* st[NSTAGE];
    sp[0] = smem;
    st[0] = smem + TILE_FLOATS;
    sp[1] = smem + 2 * TILE_FLOATS;
    st[1] = smem + 3 * TILE_FLOATS;
    uint64_t* mbar = reinterpret_cast<uint64_t*>(smem + 4 * TILE_FLOATS);

    const int tid = threadIdx.x;
    const unsigned int bid  = blockIdx.x;
    const unsigned int grid = gridDim.x;

    const unsigned int num_full = (unsigned int)(n_cells / CPB);
    // this block's tiles: bid, bid+grid, bid+2*grid, ...
    const unsigned int my_count =
        (num_full > bid) ? (num_full - 1u - bid) / grid + 1u : 0u;

    // init barriers + prologue (thread 0), then sync so waits are safe
    if (tid == 0) {
        #pragma unroll
        for (int s = 0; s < NSTAGE; s++)
            asm volatile("mbarrier.init.shared.b64 [%0], %1;"
                         :: "r"(smem_u32(&mbar[s])), "r"(1u) : "memory");
        asm volatile("fence.proxy.async.shared::cta;" ::: "memory");
        const unsigned int pro = my_count < NSTAGE ? my_count : NSTAGE;
        for (unsigned int s = 0; s < pro; s++) {
            const long long tile = (long long)(bid + s * grid);
            const uint32_t mb = smem_u32(&mbar[s]);
            asm volatile("mbarrier.arrive.expect_tx.shared.b64 _, [%0], %1;"
                         :: "r"(mb), "r"(2u * TILE_BYTES) : "memory");
            asm volatile("cp.async.bulk.shared::cta.global.mbarrier::complete_tx::bytes "
                         "[%0], [%1], %2, [%3];"
                         :: "r"(smem_u32(sp[s])), "l"(preds + tile * CPB * DD),
                            "r"((uint32_t)TILE_BYTES), "r"(mb) : "memory");
            asm volatile("cp.async.bulk.shared::cta.global.mbarrier::complete_tx::bytes "
                         "[%0], [%1], %2, [%3];"
                         :: "r"(smem_u32(st[s])), "l"(targets + tile * CPB * DD),
                            "r"((uint32_t)TILE_BYTES), "r"(mb) : "memory");
        }
    }
    __syncthreads();

    float loss = 0.0f;

    for (unsigned int j = 0; j < my_count; j++) {
        const unsigned int stage = j & 1u;
        const unsigned int phase = (j >> 1) & 1u;
        const uint32_t mb = smem_u32(&mbar[stage]);

        // wait for this stage's tile
        uint32_t done;
        do {
            asm volatile(
                "{\n\t.reg .pred p;\n\t"
                "mbarrier.try_wait.parity.acquire.cta.shared::cta.b64 p, [%1], %2, 0x989680;\n\t"
                "selp.b32 %0, 1, 0, p;\n\t}"
                : "=r"(done) : "r"(mb), "r"(phase) : "memory");
        } while (!done);

        loss += cell_loss(sp[stage] + tid * DD, st[stage] + tid * DD);

        __syncthreads();   // everyone done reading this stage's buffers

        // refill this stage with tile j+2
        if (tid == 0 && j + NSTAGE < my_count) {
            const long long tile = (long long)(bid + (j + NSTAGE) * grid);
            asm volatile("mbarrier.arrive.expect_tx.shared.b64 _, [%0], %1;"
                         :: "r"(mb), "r"(2u * TILE_BYTES) : "memory");
            asm volatile("cp.async.bulk.shared::cta.global.mbarrier::complete_tx::bytes "
                         "[%0], [%1], %2, [%3];"
                         :: "r"(smem_u32(sp[stage])), "l"(preds + tile * CPB * DD),
                            "r"((uint32_t)TILE_BYTES), "r"(mb) : "memory");
            asm volatile("cp.async.bulk.shared::cta.global.mbarrier::complete_tx::bytes "
                         "[%0], [%1], %2, [%3];"
                         :: "r"(smem_u32(st[stage])), "l"(targets + tile * CPB * DD),
                            "r"((uint32_t)TILE_BYTES), "r"(mb) : "memory");
        }
    }

    // tail cells (n_cells % CPB) — handled by block 0 with direct gmem reads
    const long long tail_start = (long long)num_full * CPB;
    if (bid == 0 && tail_start + tid < n_cells) {
        loss += cell_loss(preds   + (tail_start + tid) * DD,
                          targets + (tail_start + tid) * DD);
    }

    // block reduction: warp shuffle -> smem -> one double atomic per block
    #pragma unroll
    for (int o = 16; o > 0; o >>= 1)
        loss += __shfl_down_sync(0xffffffffu, loss, o);

    __shared__ float wsum[CPB / 32];
    __shared__ bool  is_last;
    if ((tid & 31) == 0) wsum[tid >> 5] = loss;
    __syncthreads();

    if (tid == 0) {
        float s = 0.0f;
        #pragma unroll
        for (int i = 0; i < CPB / 32; i++) s += wsum[i];
        atomicAdd(&g_acc, (double)s);
        __threadfence();
        const unsigned int prev = atomicAdd(&g_count, 1u);
        is_last = (prev == n_blocks - 1u);
    }
    __syncthreads();

    if (is_last && tid == 0) {
        out[0] = (float)(g_acc * (double)invN);
        g_acc   = 0.0;                // reset for next graph replay
        __threadfence();
        g_count = 0u;
    }
}

extern "C" void kernel_launch(void* const* d_in, const int* in_sizes, int n_in,
                              void* d_out, int out_size)
{
    const float* preds   = (const float*)d_in[0];
    const float* targets = (const float*)d_in[1];

    const long long n_cells = (long long)in_sizes[0] / DD;   // N*S*S
    const long long N = n_cells / 49;                         // S=7

    // Opt in to >48KB dynamic smem (attribute set, not an allocation; idempotent).
    cudaFuncSetAttribute(yolo_loss_kernel,
                         cudaFuncAttributeMaxDynamicSharedMemorySize,
                         SMEM_DYN_BYTES);

    const unsigned int num_tiles = (unsigned int)((n_cells + CPB - 1) / CPB);
    unsigned int grid = 148u * 3u;            // 3 blocks/SM (~61.5 KB smem each)
    if (grid > num_tiles) grid = num_tiles ? num_tiles : 1u;

    yolo_loss_kernel<<<grid, CPB, SMEM_DYN_BYTES>>>(preds, targets, n_cells, grid,
                                                    1.0f / (float)N, (float*)d_out);
}

// round 6
// speedup vs baseline: 1.0016x; 1.0016x over previous
#include <cuda_runtime.h>
#include <cstdint>

#define TPB  256       // threads per block (2 per cell)
#define CPT  128       // cells per tile
#define DD   30        // features per cell: B*5 + C
#define LAMBDA_NOOBJ 0.5f
#define NSTAGE 2

#define TILE_FLOATS (CPT * DD)            // 3840 floats per array per tile
#define TILE_BYTES  (TILE_FLOATS * 4)     // 15360 B
// dynamic smem layout: [ sp0 | st0 | sp1 | st1 | mbar[2] ]
#define SMEM_DYN_BYTES (4 * TILE_BYTES + 2 * 8)

__device__ double       g_acc;
__device__ unsigned int g_count;

__device__ __forceinline__ uint32_t smem_u32(const void* p) {
    uint32_t a;
    asm("{ .reg .u64 t; cvta.to.shared.u64 t, %1; cvt.u32.u64 %0, t; }"
        : "=r"(a) : "l"(p));
    return a;
}

// Pair-split cell loss: lanes (2k, 2k+1) cooperate on cell k. Fully uniform code
// (no divergence); returns this thread's ADDITIVE contribution — summing both
// pair threads yields the exact reference per-cell loss.
__device__ __forceinline__ float cell_loss_pair(const float* __restrict__ p,
                                                const float* __restrict__ t,
                                                int half)
{
    // ---- own box (box index == half) ----
    const int bo = half * 5;
    const float x1 = p[bo+0], y1 = p[bo+1], w1 = p[bo+2], h1 = p[bo+3];
    const float x2 = t[bo+0], y2 = t[bo+1], w2 = t[bo+2], h2 = t[bo+3];
    const float tlx = fmaxf(x1 - w1 * 0.5f, x2 - w2 * 0.5f);
    const float tly = fmaxf(y1 - h1 * 0.5f, y2 - h2 * 0.5f);
    const float brx = fminf(x1 + w1 * 0.5f, x2 + w2 * 0.5f);
    const float bry = fminf(y1 + h1 * 0.5f, y2 + h2 * 0.5f);
    const float iw = fmaxf(0.0f, brx - tlx);
    const float ih = fmaxf(0.0f, bry - tly);
    const float inter = iw * ih;
    const float iou_own = inter / (w1 * h1 + w2 * h2 - inter);

    const float iou_peer = __shfl_xor_sync(0xffffffffu, iou_own, 1);
    const float iou0 = half ? iou_peer : iou_own;
    const float iou1 = half ? iou_own  : iou_peer;
    const int bi = (iou1 > iou0) ? 1 : 0;          // first-max tie break

    // ---- own 10 classes (indices 10*half .. 10*half+9 of the 20) ----
    const int cb = 10 + half * 10;
    float cls = 0.0f;
    float m = t[cb];
    int g = half * 10;
    int has = 0;
    #pragma unroll
    for (int j = 0; j < 10; j++) {
        const float pc = p[cb + j];
        const float tc = t[cb + j];
        const float d = pc - tc;
        cls += d * d;
        has |= (tc != 0.0f) ? 1 : 0;
        if (tc > m) { m = tc; g = half * 10 + j; }
    }
    const float pm  = __shfl_xor_sync(0xffffffffu, m, 1);
    const int   pkt = __shfl_xor_sync(0xffffffffu, g | (has << 8), 1);
    const int  peer_g   = pkt & 0xff;
    const int  peer_has = pkt >> 8;
    const bool has_obj  = ((has | peer_has) & 1) != 0;

    // ascending-scan argmax: prefer lower index on ties -> choose high half only if strictly greater
    const float m0 = half ? pm : m;   const int g0 = half ? peer_g : g;
    const float m1 = half ? m  : pm;  const int g1 = half ? g : peer_g;
    const int gnd = (m1 > m0) ? g1 : g0;
    const float pg = p[10 + gnd];     // both pair lanes load same addr (broadcast)

    // ---- pos: only the owner of the best box contributes ----
    float pos_h = 0.0f;
    if (bi == half && has_obj) {
        const float dx = p[bo+0] - t[bo+0];
        const float dy = p[bo+1] - t[bo+1];
        pos_h = dx * dx + dy * dy;
    }

    // ---- conf: own box term ----
    const float cd = iou_own * pg - iou_own;       // ious*pg - ious, literal
    const float w  = (bi == half) ? 1.0f : LAMBDA_NOOBJ;
    const float conf_h = w * cd * cd;

    return cls + conf_h + pos_h;
}

// full scalar cell loss (tail path only; unused for these shapes)
__device__ __forceinline__ float cell_loss_full(const float* p, const float* t)
{
    float iou[2];
    #pragma unroll
    for (int b = 0; b < 2; b++) {
        const float x1 = p[b*5+0], y1 = p[b*5+1], w1 = p[b*5+2], h1 = p[b*5+3];
        const float x2 = t[b*5+0], y2 = t[b*5+1], w2 = t[b*5+2], h2 = t[b*5+3];
        const float tlx = fmaxf(x1 - w1 * 0.5f, x2 - w2 * 0.5f);
        const float tly = fmaxf(y1 - h1 * 0.5f, y2 - h2 * 0.5f);
        const float brx = fminf(x1 + w1 * 0.5f, x2 + w2 * 0.5f);
        const float bry = fminf(y1 + h1 * 0.5f, y2 + h2 * 0.5f);
        const float iw = fmaxf(0.0f, brx - tlx);
        const float ih = fmaxf(0.0f, bry - tly);
        const float inter = iw * ih;
        iou[b] = inter / (w1 * h1 + w2 * h2 - inter);
    }
    const int bi = (iou[1] > iou[0]) ? 1 : 0;
    float cls = 0.0f, maxtc = t[10];
    int gnd = 0; bool has_obj = false;
    #pragma unroll
    for (int j = 0; j < 20; j++) {
        const float pc = p[10 + j], tc = t[10 + j];
        const float d = pc - tc;
        cls += d * d;
        if (tc != 0.0f) has_obj = true;
        if (tc > maxtc) { maxtc = tc; gnd = j; }
    }
    const float pg = p[10 + gnd];
    const float dx = p[bi*5+0] - t[bi*5+0];
    const float dy = p[bi*5+1] - t[bi*5+1];
    const float pos = has_obj ? (dx * dx + dy * dy) : 0.0f;
    float conf = 0.0f;
    #pragma unroll
    for (int b = 0; b < 2; b++) {
        const float cd = iou[b] * pg - iou[b];
        const float w  = (b == bi) ? 1.0f : LAMBDA_NOOBJ;
        conf += w * cd * cd;
    }
    return pos + cls + conf;
}

__global__ __launch_bounds__(TPB) void yolo_loss_kernel(
    const float* __restrict__ preds,
    const float* __restrict__ targets,
    long long n_cells,
    unsigned int n_blocks,
    float invN,
    float* __restrict__ out)
{
    extern __shared__ __align__(128) float smem[];
    float* sp[NSTAGE];
    float* st[NSTAGE];
    sp[0] = smem;
    st[0] = smem + TILE_FLOATS;
    sp[1] = smem + 2 * TILE_FLOATS;
    st[1] = smem + 3 * TILE_FLOATS;
    uint64_t* mbar = reinterpret_cast<uint64_t*>(smem + 4 * TILE_FLOATS);

    const int tid  = threadIdx.x;
    const int cell = tid >> 1;          // 0..127
    const int half = tid & 1;
    const unsigned int bid  = blockIdx.x;
    const unsigned int grid = gridDim.x;

    const unsigned int num_full = (unsigned int)(n_cells / CPT);
    const unsigned int my_count =
        (num_full > bid) ? (num_full - 1u - bid) / grid + 1u : 0u;

    if (tid == 0) {
        #pragma unroll
        for (int s = 0; s < NSTAGE; s++)
            asm volatile("mbarrier.init.shared.b64 [%0], %1;"
                         :: "r"(smem_u32(&mbar[s])), "r"(1u) : "memory");
        asm volatile("fence.proxy.async.shared::cta;" ::: "memory");
        const unsigned int pro = my_count < NSTAGE ? my_count : NSTAGE;
        for (unsigned int s = 0; s < pro; s++) {
            const long long tile = (long long)(bid + s * grid);
            const uint32_t mb = smem_u32(&mbar[s]);
            asm volatile("mbarrier.arrive.expect_tx.shared.b64 _, [%0], %1;"
                         :: "r"(mb), "r"(2u * TILE_BYTES) : "memory");
            asm volatile("cp.async.bulk.shared::cta.global.mbarrier::complete_tx::bytes "
                         "[%0], [%1], %2, [%3];"
                         :: "r"(smem_u32(sp[s])), "l"(preds + tile * CPT * DD),
                            "r"((uint32_t)TILE_BYTES), "r"(mb) : "memory");
            asm volatile("cp.async.bulk.shared::cta.global.mbarrier::complete_tx::bytes "
                         "[%0], [%1], %2, [%3];"
                         :: "r"(smem_u32(st[s])), "l"(targets + tile * CPT * DD),
                            "r"((uint32_t)TILE_BYTES), "r"(mb) : "memory");
        }
    }
    __syncthreads();

    float loss = 0.0f;

    for (unsigned int j = 0; j < my_count; j++) {
        const unsigned int stage = j & 1u;
        const unsigned int phase = (j >> 1) & 1u;
        const uint32_t mb = smem_u32(&mbar[stage]);

        uint32_t done;
        do {
            asm volatile(
                "{\n\t.reg .pred p;\n\t"
                "mbarrier.try_wait.parity.acquire.cta.shared::cta.b64 p, [%1], %2, 0x989680;\n\t"
                "selp.b32 %0, 1, 0, p;\n\t}"
                : "=r"(done) : "r"(mb), "r"(phase) : "memory");
        } while (!done);

        loss += cell_loss_pair(sp[stage] + cell * DD, st[stage] + cell * DD, half);

        __syncthreads();   // everyone done reading this stage's buffers

        if (tid == 0 && j + NSTAGE < my_count) {
            const long long tile = (long long)(bid + (j + NSTAGE) * grid);
            asm volatile("mbarrier.arrive.expect_tx.shared.b64 _, [%0], %1;"
                         :: "r"(mb), "r"(2u * TILE_BYTES) : "memory");
            asm volatile("cp.async.bulk.shared::cta.global.mbarrier::complete_tx::bytes "
                         "[%0], [%1], %2, [%3];"
                         :: "r"(smem_u32(sp[stage])), "l"(preds + tile * CPT * DD),
                            "r"((uint32_t)TILE_BYTES), "r"(mb) : "memory");
            asm volatile("cp.async.bulk.shared::cta.global.mbarrier::complete_tx::bytes "
                         "[%0], [%1], %2, [%3];"
                         :: "r"(smem_u32(st[stage])), "l"(targets + tile * CPT * DD),
                            "r"((uint32_t)TILE_BYTES), "r"(mb) : "memory");
        }
    }

    // tail cells (n_cells % CPT) — block 0, direct gmem reads, scalar path
    const long long tail_start = (long long)num_full * CPT;
    if (bid == 0 && tail_start + tid < n_cells) {
        loss += cell_loss_full(preds   + (tail_start + tid) * DD,
                               targets + (tail_start + tid) * DD);
    }

    // block reduction: warp shuffle -> smem -> one double atomic per block
    #pragma unroll
    for (int o = 16; o > 0; o >>= 1)
        loss += __shfl_down_sync(0xffffffffu, loss, o);

    __shared__ float wsum[TPB / 32];
    __shared__ bool  is_last;
    if ((tid & 31) == 0) wsum[tid >> 5] = loss;
    __syncthreads();

    if (tid == 0) {
        float s = 0.0f;
        #pragma unroll
        for (int i = 0; i < TPB / 32; i++) s += wsum[i];
        atomicAdd(&g_acc, (double)s);
        __threadfence();
        const unsigned int prev = atomicAdd(&g_count, 1u);
        is_last = (prev == n_blocks - 1u);
    }
    __syncthreads();

    if (is_last && tid == 0) {
        out[0] = (float)(g_acc * (double)invN);
        g_acc   = 0.0;                // reset for next graph replay
        __threadfence();
        g_count = 0u;
    }
}

extern "C" void kernel_launch(void* const* d_in, const int* in_sizes, int n_in,
                              void* d_out, int out_size)
{
    const float* preds   = (const float*)d_in[0];
    const float* targets = (const float*)d_in[1];

    const long long n_cells = (long long)in_sizes[0] / DD;   // N*S*S
    const long long N = n_cells / 49;                         // S=7

    cudaFuncSetAttribute(yolo_loss_kernel,
                         cudaFuncAttributeMaxDynamicSharedMemorySize,
                         SMEM_DYN_BYTES);

    const unsigned int num_tiles = (unsigned int)((n_cells + CPT - 1) / CPT);
    unsigned int grid = 148u * 3u;            // 3 blocks/SM (~61.5 KB smem each)
    if (grid > num_tiles) grid = num_tiles ? num_tiles : 1u;

    yolo_loss_kernel<<<grid, TPB, SMEM_DYN_BYTES>>>(preds, targets, n_cells, grid,
                                                    1.0f / (float)N, (float*)d_out);
}